// round 10
// baseline (speedup 1.0000x reference)
#include <cuda_runtime.h>

// Problem constants
#define NL      4       // n_latents
#define MM      1024    // codes per latent
#define DD      16      // dim per latent
#define PP      16384   // points = N*H*W
#define PHALF   8192    // point pairs (p, p+8192)
#define PC      38      // p-chunks  -> 4*2*38 = 304 blocks = 2*152 SMs
#define CHUNK   216     // ceil(8192/38); last chunk = 200
#define TPTILE  36      // pairs staged in smem per inner tile
#define MTILES  2       // m tiles per latent (512 m each)
#define TPB     256     // threads per block (each owns 2 m)

typedef unsigned long long u64;

// -------- device scratch (no allocations allowed) --------
__device__ u64   g_zpack[NL * PHALF * DD];   // packed { s*z_d(p), s*z_d(p+8192) }, s = -2*alpha2
__device__ u64   g_apack[NL * PHALF];        // packed { alpha2*|z(p)|^2, alpha2*|z(p+8192)|^2 }
__device__ float g_part[PC * NL * MM];       // per-chunk partial sums of exp

// -------- f32x2 helpers (sm_103a packed fp32; PTX-only) --------
__device__ __forceinline__ u64 pack2(float a, float b) {
    u64 r; asm("mov.b64 %0, {%1, %2};" : "=l"(r) : "f"(a), "f"(b)); return r;
}
__device__ __forceinline__ void unpack2(u64 v, float& a, float& b) {
    asm("mov.b64 {%0, %1}, %2;" : "=f"(a), "=f"(b) : "l"(v));
}
__device__ __forceinline__ u64 fma2(u64 a, u64 b, u64 c) {
    u64 r; asm("fma.rn.f32x2 %0, %1, %2, %3;" : "=l"(r) : "l"(a), "l"(b), "l"(c)); return r;
}
__device__ __forceinline__ u64 add2(u64 a, u64 b) {
    u64 r; asm("add.rn.f32x2 %0, %1, %2;" : "=l"(r) : "l"(a), "l"(b)); return r;
}
__device__ __forceinline__ float ex2(float x) {
    float r; asm("ex2.approx.f32 %0, %1;" : "=f"(r) : "f"(x)); return r;
}

__device__ __forceinline__ float get_alpha2(const float* lsp) {
    // alpha = -1/(2*exp(ls)^2) = -0.5*exp(-2 ls);  alpha2 = alpha * log2(e)
    float ls = lsp[0];
    return -0.5f * expf(-2.0f * ls) * 1.4426950408889634f;
}

// ============================================================
// Kernel 1: stage z -> packed point-pair layout, pre-scaled.
//   zr[l,p,d] = z[n, l*16+d, h, w],  p = n*1024 + h*32 + w
//   pair (p, p+8192) shares hw, differs in n by 8.
// ============================================================
__global__ void stage_kernel(const float* __restrict__ z, const float* __restrict__ lsp) {
    int gid = blockIdx.x * blockDim.x + threadIdx.x;   // gid = l*PHALF + ph
    if (gid >= NL * PHALF) return;
    float alpha2 = get_alpha2(lsp);
    float s = -2.0f * alpha2;

    int l  = gid >> 13;          // /8192
    int ph = gid & (PHALF - 1);
    int n0 = ph >> 10;
    int hw = ph & 1023;

    const float* zp0 = z + n0 * 65536 + (l * DD) * 1024 + hw;
    const float* zp1 = zp0 + 8 * 65536;  // point ph + 8192 (n -> n+8, same hw)

    float sq0 = 0.0f, sq1 = 0.0f;
    u64 base = (u64)gid * DD;
    #pragma unroll
    for (int d = 0; d < DD; ++d) {
        float a = zp0[d << 10];
        float b = zp1[d << 10];
        sq0 = fmaf(a, a, sq0);
        sq1 = fmaf(b, b, sq1);
        g_zpack[base + d] = pack2(s * a, s * b);
    }
    g_apack[gid] = pack2(alpha2 * sq0, alpha2 * sq1);
}

// ============================================================
// Kernel 2: fused distance + exp + point-sum.
//   Each thread owns 2 codes (m0, m1); each f32x2 lane-pair is
//   2 points.  arg = a_pair + c_m + dot(z_scaled, e)  (all folded)
//   sum += exp2(arg).
// ============================================================
__global__ void __launch_bounds__(TPB, 2)
main_kernel(const float* __restrict__ e, const float* __restrict__ lsp) {
    __shared__ __align__(16) u64 s_z[TPTILE * DD];
    __shared__ u64 s_a[TPTILE];

    const int tid = threadIdx.x;
    const int b   = blockIdx.x;
    const int pc  = b % PC;
    const int mt  = (b / PC) & (MTILES - 1);
    const int l   = b / (PC * MTILES);

    const float alpha2 = get_alpha2(lsp);

    const int m0 = mt * (2 * TPB) + tid;
    const int m1 = m0 + TPB;

    // e rows into registers, pre-packed {e,e}; c_m = alpha2*|e_m|^2
    u64 e0[DD], e1[DD];
    float esq0 = 0.0f, esq1 = 0.0f;
    const float4* ep0 = (const float4*)(e + ((l << 10) + m0) * DD);
    const float4* ep1 = (const float4*)(e + ((l << 10) + m1) * DD);
    #pragma unroll
    for (int j = 0; j < 4; ++j) {
        float4 q = ep0[j];
        esq0 += q.x * q.x + q.y * q.y + q.z * q.z + q.w * q.w;
        e0[4 * j + 0] = pack2(q.x, q.x);
        e0[4 * j + 1] = pack2(q.y, q.y);
        e0[4 * j + 2] = pack2(q.z, q.z);
        e0[4 * j + 3] = pack2(q.w, q.w);
        float4 r = ep1[j];
        esq1 += r.x * r.x + r.y * r.y + r.z * r.z + r.w * r.w;
        e1[4 * j + 0] = pack2(r.x, r.x);
        e1[4 * j + 1] = pack2(r.y, r.y);
        e1[4 * j + 2] = pack2(r.z, r.z);
        e1[4 * j + 3] = pack2(r.w, r.w);
    }
    const u64 cm0 = pack2(alpha2 * esq0, alpha2 * esq0);
    const u64 cm1 = pack2(alpha2 * esq1, alpha2 * esq1);

    float s00 = 0.0f, s01 = 0.0f, s10 = 0.0f, s11 = 0.0f;

    const int prStart = pc * CHUNK;
    const int prEnd   = min(prStart + CHUNK, PHALF);

    for (int pr = prStart; pr < prEnd; pr += TPTILE) {
        const int tp = min(TPTILE, prEnd - pr);
        __syncthreads();
        {
            const int zb = (l * PHALF + pr) * DD;
            for (int idx = tid; idx < tp * DD; idx += TPB)
                s_z[idx] = g_zpack[zb + idx];
            if (tid < tp)
                s_a[tid] = g_apack[l * PHALF + pr + tid];
        }
        __syncthreads();

        for (int i = 0; i < tp; ++i) {
            const ulonglong2* zr = (const ulonglong2*)(s_z + i * DD);
            const u64 a = s_a[i];
            u64 acc0 = add2(a, cm0);
            u64 acc1 = add2(a, cm1);
            #pragma unroll
            for (int k = 0; k < 8; ++k) {
                ulonglong2 zz = zr[k];
                acc0 = fma2(zz.x, e0[2 * k + 0], acc0);
                acc1 = fma2(zz.x, e1[2 * k + 0], acc1);
                acc0 = fma2(zz.y, e0[2 * k + 1], acc0);
                acc1 = fma2(zz.y, e1[2 * k + 1], acc1);
            }
            float x0, x1, y0, y1;
            unpack2(acc0, x0, x1);
            unpack2(acc1, y0, y1);
            s00 += ex2(x0); s01 += ex2(x1);
            s10 += ex2(y0); s11 += ex2(y1);
        }
    }

    g_part[(pc * NL + l) * MM + m0] = s00 + s01;
    g_part[(pc * NL + l) * MM + m1] = s10 + s11;
}

// ============================================================
// Kernel 3: reduce partials -> log -> means -> scalar loss.
//   loss = C - (1/(L*M)) * sum_{l,m} ln(S_lm)
//   C = 32*(2*ls - 1) + ln(16384)
// ============================================================
__global__ void final_kernel(const float* __restrict__ lsp, float* __restrict__ out) {
    __shared__ float red[1024];
    const int t = threadIdx.x;   // = m
    float local = 0.0f;
    #pragma unroll
    for (int l = 0; l < NL; ++l) {
        float s = 0.0f;
        #pragma unroll
        for (int pc = 0; pc < PC; ++pc)
            s += g_part[(pc * NL + l) * MM + t];
        local += logf(s);
    }
    red[t] = local;
    __syncthreads();
    for (int o = 512; o > 0; o >>= 1) {
        if (t < o) red[t] += red[t + o];
        __syncthreads();
    }
    if (t == 0) {
        float ls = lsp[0];
        float C = 32.0f * (2.0f * ls - 1.0f) + 9.7040605278392f;  // ln(16384)
        out[0] = C - red[0] / 4096.0f;
    }
}

extern "C" void kernel_launch(void* const* d_in, const int* in_sizes, int n_in,
                              void* d_out, int out_size) {
    const float* z  = (const float*)d_in[0];  // (16,64,32,32) f32
    const float* e  = (const float*)d_in[1];  // (4,1024,16)   f32
    const float* ls = (const float*)d_in[2];  // (1,)          f32
    float* out = (float*)d_out;

    stage_kernel<<<(NL * PHALF + 127) / 128, 128>>>(z, ls);
    main_kernel<<<NL * MTILES * PC, TPB>>>(e, ls);
    final_kernel<<<1, 1024>>>(ls, out);
}

// round 11
// speedup vs baseline: 1.0044x; 1.0044x over previous
#include <cuda_runtime.h>

// Problem constants
#define NL      4       // n_latents
#define MM      1024    // codes per latent
#define DD      16      // dim per latent
#define PP      16384   // points = N*H*W
#define PHALF   8192    // point pairs (p, p+8192)
#define PC      38      // p-chunks  -> 4*2*38 = 304 blocks = 2*152 SMs
#define CHUNK   216     // ceil(8192/38); last chunk = 200
#define TPTILE  36      // pairs staged in smem per inner tile
#define MTILES  2       // m tiles per latent (512 m each)
#define TPB     256     // threads per block (each owns 2 m)

typedef unsigned long long u64;

// -------- device scratch (no allocations allowed) --------
__device__ u64   g_zpack[NL * PHALF * DD];   // packed { s*z_d(p), s*z_d(p+8192) }, s = -2*alpha2
__device__ u64   g_apack[NL * PHALF];        // packed { alpha2*|z(p)|^2, alpha2*|z(p+8192)|^2 }
__device__ float g_part[PC * NL * MM];       // per-chunk partial sums of exp

// -------- f32x2 helpers (sm_103a packed fp32; PTX-only) --------
__device__ __forceinline__ u64 pack2(float a, float b) {
    u64 r; asm("mov.b64 %0, {%1, %2};" : "=l"(r) : "f"(a), "f"(b)); return r;
}
__device__ __forceinline__ void unpack2(u64 v, float& a, float& b) {
    asm("mov.b64 {%0, %1}, %2;" : "=f"(a), "=f"(b) : "l"(v));
}
__device__ __forceinline__ u64 fma2(u64 a, u64 b, u64 c) {
    u64 r; asm("fma.rn.f32x2 %0, %1, %2, %3;" : "=l"(r) : "l"(a), "l"(b), "l"(c)); return r;
}
__device__ __forceinline__ u64 add2(u64 a, u64 b) {
    u64 r; asm("add.rn.f32x2 %0, %1, %2;" : "=l"(r) : "l"(a), "l"(b)); return r;
}
__device__ __forceinline__ float ex2(float x) {
    float r; asm("ex2.approx.f32 %0, %1;" : "=f"(r) : "f"(x)); return r;
}

__device__ __forceinline__ float get_alpha2(const float* lsp) {
    // alpha = -1/(2*exp(ls)^2) = -0.5*exp(-2 ls);  alpha2 = alpha * log2(e)
    float ls = lsp[0];
    return -0.5f * expf(-2.0f * ls) * 1.4426950408889634f;
}

// ============================================================
// Kernel 1: stage z -> packed point-pair layout, pre-scaled.
//   zr[l,p,d] = z[n, l*16+d, h, w],  p = n*1024 + h*32 + w
//   pair (p, p+8192) shares hw, differs in n by 8.
// ============================================================
__global__ void stage_kernel(const float* __restrict__ z, const float* __restrict__ lsp) {
    int gid = blockIdx.x * blockDim.x + threadIdx.x;   // gid = l*PHALF + ph
    if (gid >= NL * PHALF) return;
    float alpha2 = get_alpha2(lsp);
    float s = -2.0f * alpha2;

    int l  = gid >> 13;          // /8192
    int ph = gid & (PHALF - 1);
    int n0 = ph >> 10;
    int hw = ph & 1023;

    const float* zp0 = z + n0 * 65536 + (l * DD) * 1024 + hw;
    const float* zp1 = zp0 + 8 * 65536;  // point ph + 8192 (n -> n+8, same hw)

    float sq0 = 0.0f, sq1 = 0.0f;
    u64 base = (u64)gid * DD;
    #pragma unroll
    for (int d = 0; d < DD; ++d) {
        float a = zp0[d << 10];
        float b = zp1[d << 10];
        sq0 = fmaf(a, a, sq0);
        sq1 = fmaf(b, b, sq1);
        g_zpack[base + d] = pack2(s * a, s * b);
    }
    g_apack[gid] = pack2(alpha2 * sq0, alpha2 * sq1);
}

// ============================================================
// Kernel 2: fused distance + exp + point-sum.
//   Each thread owns 2 codes (m0, m1); each f32x2 lane-pair is
//   2 points.  arg = a_pair + c_m + dot(z_scaled, e)  (all folded)
//   sum += exp2(arg).
// ============================================================
__global__ void __launch_bounds__(TPB, 2)
main_kernel(const float* __restrict__ e, const float* __restrict__ lsp) {
    __shared__ __align__(16) u64 s_z[TPTILE * DD];
    __shared__ u64 s_a[TPTILE];

    const int tid = threadIdx.x;
    const int b   = blockIdx.x;
    const int pc  = b % PC;
    const int mt  = (b / PC) & (MTILES - 1);
    const int l   = b / (PC * MTILES);

    const float alpha2 = get_alpha2(lsp);

    const int m0 = mt * (2 * TPB) + tid;
    const int m1 = m0 + TPB;

    // e rows into registers, pre-packed {e,e}; c_m = alpha2*|e_m|^2
    u64 e0[DD], e1[DD];
    float esq0 = 0.0f, esq1 = 0.0f;
    const float4* ep0 = (const float4*)(e + ((l << 10) + m0) * DD);
    const float4* ep1 = (const float4*)(e + ((l << 10) + m1) * DD);
    #pragma unroll
    for (int j = 0; j < 4; ++j) {
        float4 q = ep0[j];
        esq0 += q.x * q.x + q.y * q.y + q.z * q.z + q.w * q.w;
        e0[4 * j + 0] = pack2(q.x, q.x);
        e0[4 * j + 1] = pack2(q.y, q.y);
        e0[4 * j + 2] = pack2(q.z, q.z);
        e0[4 * j + 3] = pack2(q.w, q.w);
        float4 r = ep1[j];
        esq1 += r.x * r.x + r.y * r.y + r.z * r.z + r.w * r.w;
        e1[4 * j + 0] = pack2(r.x, r.x);
        e1[4 * j + 1] = pack2(r.y, r.y);
        e1[4 * j + 2] = pack2(r.z, r.z);
        e1[4 * j + 3] = pack2(r.w, r.w);
    }
    const u64 cm0 = pack2(alpha2 * esq0, alpha2 * esq0);
    const u64 cm1 = pack2(alpha2 * esq1, alpha2 * esq1);

    float s00 = 0.0f, s01 = 0.0f, s10 = 0.0f, s11 = 0.0f;

    const int prStart = pc * CHUNK;
    const int prEnd   = min(prStart + CHUNK, PHALF);

    for (int pr = prStart; pr < prEnd; pr += TPTILE) {
        const int tp = min(TPTILE, prEnd - pr);
        __syncthreads();
        {
            const int zb = (l * PHALF + pr) * DD;
            for (int idx = tid; idx < tp * DD; idx += TPB)
                s_z[idx] = g_zpack[zb + idx];
            if (tid < tp)
                s_a[tid] = g_apack[l * PHALF + pr + tid];
        }
        __syncthreads();

        for (int i = 0; i < tp; ++i) {
            const ulonglong2* zr = (const ulonglong2*)(s_z + i * DD);
            const u64 a = s_a[i];
            u64 acc0 = add2(a, cm0);
            u64 acc1 = add2(a, cm1);
            #pragma unroll
            for (int k = 0; k < 8; ++k) {
                ulonglong2 zz = zr[k];
                acc0 = fma2(zz.x, e0[2 * k + 0], acc0);
                acc1 = fma2(zz.x, e1[2 * k + 0], acc1);
                acc0 = fma2(zz.y, e0[2 * k + 1], acc0);
                acc1 = fma2(zz.y, e1[2 * k + 1], acc1);
            }
            float x0, x1, y0, y1;
            unpack2(acc0, x0, x1);
            unpack2(acc1, y0, y1);
            s00 += ex2(x0); s01 += ex2(x1);
            s10 += ex2(y0); s11 += ex2(y1);
        }
    }

    g_part[(pc * NL + l) * MM + m0] = s00 + s01;
    g_part[(pc * NL + l) * MM + m1] = s10 + s11;
}

// ============================================================
// Kernel 3: reduce partials -> log -> means -> scalar loss.
//   loss = C - (1/(L*M)) * sum_{l,m} ln(S_lm)
//   C = 32*(2*ls - 1) + ln(16384)
// ============================================================
__global__ void final_kernel(const float* __restrict__ lsp, float* __restrict__ out) {
    __shared__ float red[1024];
    const int t = threadIdx.x;   // = m
    float local = 0.0f;
    #pragma unroll
    for (int l = 0; l < NL; ++l) {
        float s = 0.0f;
        #pragma unroll
        for (int pc = 0; pc < PC; ++pc)
            s += g_part[(pc * NL + l) * MM + t];
        local += logf(s);
    }
    red[t] = local;
    __syncthreads();
    for (int o = 512; o > 0; o >>= 1) {
        if (t < o) red[t] += red[t + o];
        __syncthreads();
    }
    if (t == 0) {
        float ls = lsp[0];
        float C = 32.0f * (2.0f * ls - 1.0f) + 9.7040605278392f;  // ln(16384)
        out[0] = C - red[0] / 4096.0f;
    }
}

extern "C" void kernel_launch(void* const* d_in, const int* in_sizes, int n_in,
                              void* d_out, int out_size) {
    const float* z  = (const float*)d_in[0];  // (16,64,32,32) f32
    const float* e  = (const float*)d_in[1];  // (4,1024,16)   f32
    const float* ls = (const float*)d_in[2];  // (1,)          f32
    float* out = (float*)d_out;

    stage_kernel<<<(NL * PHALF + 127) / 128, 128>>>(z, ls);
    main_kernel<<<NL * MTILES * PC, TPB>>>(e, ls);
    final_kernel<<<1, 1024>>>(ls, out);
}